// round 14
// baseline (speedup 1.0000x reference)
#include <cuda_runtime.h>
#include <cuda_fp16.h>
#include <cstdint>
#include <math.h>

#define B_   16
#define N_   2048
#define FIN  256
#define H_   128
#define TJ   64
#define NTILE (N_ / TJ)      // 32

// Scratch (allocation-free: __device__ globals)
__device__ half     g_whT[B_ * H_ * N_];      // [b][h][n] fp16
__device__ float    g_src[B_ * N_];           // src + b_a folded in
__device__ float    g_dst[B_ * N_];
__device__ float    g_dstmax[B_];
__device__ float2   g_ed[B_ * N_];            // (exp(dst), exp(0.01*dst))
__device__ uint32_t g_adjb[B_ * N_ * 64];     // bit-packed adj, 64 u32 per row

__device__ __forceinline__ uint32_t smem_u32(const void* p) {
    uint32_t a;
    asm("{ .reg .u64 t; cvta.to.shared.u64 t, %1; cvt.u32.u64 %0, t; }" : "=r"(a) : "l"(p));
    return a;
}

#define LDSM4(r0, r1, r2, r3, addr) \
    asm volatile("ldmatrix.sync.aligned.m8n8.x4.shared.b16 {%0,%1,%2,%3}, [%4];" \
                 : "=r"(r0), "=r"(r1), "=r"(r2), "=r"(r3) : "r"(addr))

#define MMA16816(d, a0, a1, a2, a3, b0, b1) \
    asm volatile("mma.sync.aligned.m16n8k16.row.col.f32.f16.f16.f32 " \
                 "{%0,%1,%2,%3}, {%4,%5,%6,%7}, {%8,%9}, {%0,%1,%2,%3};" \
                 : "+f"((d)[0]), "+f"((d)[1]), "+f"((d)[2]), "+f"((d)[3]) \
                 : "r"(a0), "r"(a1), "r"(a2), "r"(a3), "r"(b0), "r"(b1))

#define CP_ASYNC16(dst, src) \
    asm volatile("cp.async.cg.shared.global [%0], [%1], 16;" :: "r"(dst), "l"(src))
#define CP_COMMIT()  asm volatile("cp.async.commit_group;" ::: "memory")
#define CP_WAIT0()   asm volatile("cp.async.wait_group 0;" ::: "memory")

// ---------------------------------------------------------------------------
// Pack phase: 128 rows (1MB adj) -> 8192 bitmasks. 32 masks/thread, MLP=16.
// adj values are exactly 0/1, so mask accumulates v<<k via IMAD.
// ---------------------------------------------------------------------------
__device__ __forceinline__ uint32_t pack32(const int4* a) {
    uint32_t m = 0;
#pragma unroll
    for (int u = 0; u < 8; u++) {
        int4 v = a[u];
        uint32_t nib = (uint32_t)(v.x + v.y * 2 + v.z * 4 + v.w * 8);
        m += nib << (4 * u);
    }
    return m;
}

__device__ __forceinline__ void pack_block(const int* __restrict__ adj, int row0, int t) {
    const int4* slab = (const int4*)(adj + (size_t)row0 * N_);   // 65536 int4
    uint32_t*   ob   = g_adjb + (size_t)row0 * 64;               // 8192 u32
#pragma unroll
    for (int g = 0; g < 8; g++) {
        int mbase = g * 1024 + t * 4;      // 4 consecutive masks per thread
        int4 a[16];
#pragma unroll
        for (int u = 0; u < 16; u++) a[u] = slab[(size_t)mbase * 8 + u];
        uint32_t m0 = pack32(a);
        uint32_t m1 = pack32(a + 8);
#pragma unroll
        for (int u = 0; u < 16; u++) a[u] = slab[(size_t)(mbase + 2) * 8 + u];
        uint32_t m2 = pack32(a);
        uint32_t m3 = pack32(a + 8);
        *(uint4*)(ob + mbase) = make_uint4(m0, m1, m2, m3);
    }
}

// ---------------------------------------------------------------------------
// Kernel A (fused): GEMM (wh in regs -> whT fp16 + src/dst) + adj pack phase.
// Block-phase stagger: bid<148 do GEMM->pack, bid>=148 do pack->GEMM, so the
// two co-resident CTAs on an SM overlap compute with DRAM streaming.
// ---------------------------------------------------------------------------
__global__ __launch_bounds__(256, 2) void k_proj(const float* __restrict__ inp,
                                                 const float* __restrict__ W,
                                                 const float* __restrict__ bW,
                                                 const float* __restrict__ av,
                                                 const float* __restrict__ b_a,
                                                 const int* __restrict__ adj) {
    __shared__ __align__(16) float A_s[32 * 132];
    __shared__ __align__(16) float W_s[32 * 132];
    int t = threadIdx.x;
    int row0 = blockIdx.x * 128;
    int tr = t >> 4, tc = t & 15;

    bool pack_first = (blockIdx.x >= 148);
    if (pack_first) pack_block(adj, row0, t);

    float acc[8][8];
#pragma unroll
    for (int i = 0; i < 8; i++)
#pragma unroll
        for (int j = 0; j < 8; j++) acc[i][j] = 0.f;

    for (int k0 = 0; k0 < FIN; k0 += 32) {
#pragma unroll
        for (int v = 0; v < 4; v++) {
            int f4 = t + 256 * v;
            int r = f4 >> 3;
            int c = (f4 & 7) * 4;
            float4 a4 = *(const float4*)(inp + (size_t)(row0 + r) * FIN + k0 + c);
            A_s[(c + 0) * 132 + r] = a4.x;
            A_s[(c + 1) * 132 + r] = a4.y;
            A_s[(c + 2) * 132 + r] = a4.z;
            A_s[(c + 3) * 132 + r] = a4.w;
            float4 b4 = *(const float4*)(W + (size_t)r * FIN + k0 + c);
            W_s[(c + 0) * 132 + r] = b4.x;
            W_s[(c + 1) * 132 + r] = b4.y;
            W_s[(c + 2) * 132 + r] = b4.z;
            W_s[(c + 3) * 132 + r] = b4.w;
        }
        __syncthreads();
#pragma unroll
        for (int kk = 0; kk < 32; kk++) {
            float a[8], b[8];
            *(float4*)&a[0] = *(const float4*)&A_s[kk * 132 + tr * 8];
            *(float4*)&a[4] = *(const float4*)&A_s[kk * 132 + tr * 8 + 4];
            *(float4*)&b[0] = *(const float4*)&W_s[kk * 132 + tc * 8];
            *(float4*)&b[4] = *(const float4*)&W_s[kk * 132 + tc * 8 + 4];
#pragma unroll
            for (int i = 0; i < 8; i++)
#pragma unroll
                for (int j = 0; j < 8; j++)
                    acc[i][j] = fmaf(a[i], b[j], acc[i][j]);
        }
        __syncthreads();
    }

    // ---- epilogue ----
    int h0 = tc * 8;
    int bb = row0 / N_;
    int n0 = (row0 % N_) + tr * 8;

    float bwv[8];
    *(float4*)&bwv[0] = *(const float4*)(bW + h0);
    *(float4*)&bwv[4] = *(const float4*)(bW + h0 + 4);
#pragma unroll
    for (int i = 0; i < 8; i++)
#pragma unroll
        for (int j = 0; j < 8; j++) acc[i][j] += bwv[j];

    // whT transposed fp16 stores
#pragma unroll
    for (int j = 0; j < 8; j++) {
        __align__(16) half hi8[8];
#pragma unroll
        for (int i = 0; i < 8; i++) hi8[i] = __float2half_rn(acc[i][j]);
        size_t idx = ((size_t)(bb * H_ + h0 + j)) * N_ + n0;
        *(uint4*)(g_whT + idx) = *(uint4*)hi8;
    }

    // src/dst reductions
    float a1v[8], a2v[8];
    *(float4*)&a1v[0] = *(const float4*)(av + h0);
    *(float4*)&a1v[4] = *(const float4*)(av + h0 + 4);
    *(float4*)&a2v[0] = *(const float4*)(av + H_ + h0);
    *(float4*)&a2v[4] = *(const float4*)(av + H_ + h0 + 4);

    float s1[8], s2[8];
#pragma unroll
    for (int i = 0; i < 8; i++) {
        float x1 = 0.f, x2 = 0.f;
#pragma unroll
        for (int j = 0; j < 8; j++) {
            x1 = fmaf(acc[i][j], a1v[j], x1);
            x2 = fmaf(acc[i][j], a2v[j], x2);
        }
        s1[i] = x1; s2[i] = x2;
    }
#pragma unroll
    for (int o = 1; o < 16; o <<= 1) {
#pragma unroll
        for (int i = 0; i < 8; i++) {
            s1[i] += __shfl_xor_sync(~0u, s1[i], o);
            s2[i] += __shfl_xor_sync(~0u, s2[i], o);
        }
    }
    if (tc == 0) {
        float ba = b_a[0];
        int r = row0 + tr * 8;
#pragma unroll
        for (int i = 0; i < 8; i++) {
            g_src[r + i] = s1[i] + ba;
            g_dst[r + i] = s2[i];
        }
    }

    if (!pack_first) pack_block(adj, row0, t);
}

// ---------------------------------------------------------------------------
// Kernel B2: per-batch dst max + exp tables ed1 = exp(dst), ed0 = exp(.01 dst)
// ---------------------------------------------------------------------------
__global__ __launch_bounds__(256) void k_prep() {
    __shared__ float red[8];
    int b = blockIdx.x, t = threadIdx.x;
    float mx = -1e30f;
#pragma unroll
    for (int v = 0; v < 8; v++) {
        int idx = b * N_ + t + 256 * v;
        float d = g_dst[idx];
        mx = fmaxf(mx, d);
        g_ed[idx] = make_float2(__expf(d), __expf(0.01f * d));
    }
#pragma unroll
    for (int o = 16; o; o >>= 1) mx = fmaxf(mx, __shfl_xor_sync(~0u, mx, o));
    if ((t & 31) == 0) red[t >> 5] = mx;
    __syncthreads();
    if (t == 0) {
        float m2 = red[0];
#pragma unroll
        for (int i = 1; i < 8; i++) m2 = fmaxf(m2, red[i]);
        g_dstmax[b] = m2;
    }
}

// ---------------------------------------------------------------------------
// Kernel C: fused attention. Score phase has NO exp (table factorization):
//   p = mask ? (ed1[j] > X1 ? E1*ed1[j] : E0*ed0[j]) : 0
//
// smem: Ph[2]: 0,18432  W[2]: 36864,55296  ed: 73728 (16KB)  l_s: 90112
// total 90624.  Row stride 144B (ldmatrix conflict-free).
// ---------------------------------------------------------------------------
#define PB   18432u
#define OWH  36864u
#define OED  73728u
#define OLS  90112u
#define DYNB 90624

__global__ __launch_bounds__(256, 2) void k_attn_mma(float* __restrict__ out) {
    extern __shared__ __align__(16) char dyn[];
    uint32_t sb = smem_u32(dyn);

    int t = threadIdx.x;
    int w = t >> 5, lane = t & 31;
    int ti = t >> 1, q = t & 1;
    int b = blockIdx.y;
    int ibase = blockIdx.x * 128;

    float my_src = g_src[b * N_ + ibase + ti];
    float mb = my_src + g_dstmax[b];
    float m = mb > 0.f ? mb : 0.01f * mb;
    float E1 = __expf(my_src - m);
    float E0 = __expf(0.01f * my_src - m);
    float X1 = __expf(-my_src);
    float l = 0.f;

    const uint32_t* adjb_row = g_adjb + (size_t)(b * N_ + ibase + ti) * 64;
    const half*     whT_b    = g_whT + (size_t)b * H_ * N_;

    float C[16][4];
#pragma unroll
    for (int nt = 0; nt < 16; nt++)
#pragma unroll
        for (int c = 0; c < 4; c++) C[nt][c] = 0.f;

    // ldmatrix base addresses (buffer 0), row stride 144B
    uint32_t a_base = sb + (16 * w + (lane & 15)) * 144 + (lane >> 4) * 16;  // Ph
    int bn = ((lane >> 4) & 1) * 8 + (lane & 7);
    int bk = ((lane >> 3) & 1) * 8;
    uint32_t b_base = sb + OWH + bn * 144 + bk * 2;                           // W

    // W staging: 2 threads per row, 4 x 16B chunks each (128B/row)
    int hr = t >> 1, hf = t & 1;
    uint32_t wdst = sb + OWH + hr * 144 + hf * 64;
    const half* wsrc = whT_b + (size_t)hr * N_ + hf * 32;

    // ---- prologue: stage W(0), ed table -> smem, mask(0) ----
#pragma unroll
    for (int k = 0; k < 4; k++) CP_ASYNC16(wdst + k * 16, wsrc + k * 8);
    CP_COMMIT();
    {
        float4* ds = (float4*)(dyn + OED);
        const float4* g4 = (const float4*)(g_ed + b * N_);
#pragma unroll
        for (int k = 0; k < 4; k++) ds[t + 256 * k] = g4[t + 256 * k];
    }
    uint32_t mnext = adjb_row[q];
    __syncthreads();   // ed_s visible

    for (int tile = 0; tile < NTILE; tile++) {
        int s = tile & 1;
        int j0 = tile * TJ;

        // ---- score phase: 32 j's = [j0 + q*32, +32) for row ti ----
        {
            uint32_t mask = mnext;
            if (tile < NTILE - 1) mnext = adjb_row[(tile + 1) * 2 + q];

            const float4* e4 = (const float4*)(dyn + OED) + ((j0 + q * 32) >> 1);
            __align__(16) half hs[32];
#pragma unroll
            for (int v = 0; v < 16; v++) {       // 2 j's per float4 (e1,e0,e1,e0)
                float4 ee = e4[v];
                float pa = (ee.x > X1) ? E1 * ee.x : E0 * ee.y;
                float pb = (ee.z > X1) ? E1 * ee.z : E0 * ee.w;
                pa = (mask >> (2 * v + 0)) & 1 ? pa : 0.f;
                pb = (mask >> (2 * v + 1)) & 1 ? pb : 0.f;
                l += pa + pb;
                *(half2*)&hs[2 * v] = __floats2half2_rn(pa, pb);
            }
            uint32_t poff = s * PB + ti * 144 + q * 64;
#pragma unroll
            for (int k = 0; k < 4; k++)
                *(uint4*)(dyn + poff + k * 16) = ((uint4*)hs)[k];
        }

        CP_WAIT0();        // W(tile) landed
        __syncthreads();   // P(s) visible; MMA(tile-1) done with buffer s^1

        // ---- stage W(tile+1) into buffer s^1 (overlaps MMA) ----
        if (tile < NTILE - 1) {
            int jn = (tile + 1) * TJ;
            uint32_t off = (s ^ 1) * PB;
#pragma unroll
            for (int k = 0; k < 4; k++) CP_ASYNC16(wdst + off + k * 16, wsrc + jn + k * 8);
            CP_COMMIT();
        }

        // ---- MMA phase on buffer s: 4 k16 chunks ----
        uint32_t aoff = s * PB;
#pragma unroll
        for (int kc = 0; kc < 4; kc++) {
            uint32_t Ah0, Ah1, Ah2, Ah3;
            LDSM4(Ah0, Ah1, Ah2, Ah3, a_base + aoff + kc * 32);
#pragma unroll
            for (int np = 0; np < 8; np++) {
                uint32_t Bh0, Bh1, Bh2, Bh3;
                LDSM4(Bh0, Bh1, Bh2, Bh3, b_base + aoff + np * (16 * 144) + kc * 32);
                MMA16816(C[np * 2 + 0], Ah0, Ah1, Ah2, Ah3, Bh0, Bh1);
                MMA16816(C[np * 2 + 1], Ah0, Ah1, Ah2, Ah3, Bh2, Bh3);
            }
        }
    }

    l += __shfl_xor_sync(~0u, l, 1);
    float* l_s = (float*)(dyn + OLS);
    if (q == 0) l_s[ti] = l;
    __syncthreads();

    // ---- epilogue: normalize, ELU, store from fragments ----
    {
        int r0 = 16 * w + (lane >> 2);
        int r1 = r0 + 8;
        float inv0 = 1.0f / l_s[r0];
        float inv1 = 1.0f / l_s[r1];
        float* orow0 = out + ((size_t)(b * N_ + ibase + r0)) * H_;
        float* orow1 = out + ((size_t)(b * N_ + ibase + r1)) * H_;
        int hoff = (lane & 3) * 2;
#pragma unroll
        for (int nt = 0; nt < 16; nt++) {
            int h = nt * 8 + hoff;
            float x;
            float2 o;
            x = C[nt][0] * inv0; o.x = x > 0.f ? x : expm1f(x);
            x = C[nt][1] * inv0; o.y = x > 0.f ? x : expm1f(x);
            *(float2*)(orow0 + h) = o;
            x = C[nt][2] * inv1; o.x = x > 0.f ? x : expm1f(x);
            x = C[nt][3] * inv1; o.y = x > 0.f ? x : expm1f(x);
            *(float2*)(orow1 + h) = o;
        }
    }
}

// ---------------------------------------------------------------------------
extern "C" void kernel_launch(void* const* d_in, const int* in_sizes, int n_in,
                              void* d_out, int out_size) {
    const float* inputs = (const float*)d_in[0];
    const int*   adj    = (const int*)d_in[1];
    const float* W      = (const float*)d_in[2];
    const float* bW     = (const float*)d_in[3];
    const float* a      = (const float*)d_in[4];
    const float* b_a    = (const float*)d_in[5];
    float* out = (float*)d_out;

    cudaFuncSetAttribute(k_attn_mma, cudaFuncAttributeMaxDynamicSharedMemorySize, DYNB);

    k_proj<<<(B_ * N_) / 128, 256>>>(inputs, W, bW, a, b_a, adj);
    k_prep<<<B_, 256>>>();
    k_attn_mma<<<dim3(N_ / 128, B_), 256, DYNB>>>(out);
}

// round 15
// speedup vs baseline: 1.0991x; 1.0991x over previous
#include <cuda_runtime.h>
#include <cuda_fp16.h>
#include <cstdint>
#include <math.h>

#define B_   16
#define N_   2048
#define FIN  256
#define H_   128
#define TJ   64
#define NTILE (N_ / TJ)      // 32

typedef unsigned long long ull;

// Scratch (allocation-free: __device__ globals)
__device__ half     g_whT[B_ * H_ * N_];      // [b][h][n] fp16
__device__ float    g_src[B_ * N_];           // src + b_a folded in
__device__ float    g_dst[B_ * N_];
__device__ float    g_dstmax[B_];
__device__ float2   g_ed[B_ * N_];            // (exp(dst), exp(0.01*dst))
__device__ uint32_t g_adjb[B_ * N_ * 64];     // bit-packed adj, 64 u32 per row

__device__ __forceinline__ uint32_t smem_u32(const void* p) {
    uint32_t a;
    asm("{ .reg .u64 t; cvta.to.shared.u64 t, %1; cvt.u32.u64 %0, t; }" : "=r"(a) : "l"(p));
    return a;
}

#define LDSM4(r0, r1, r2, r3, addr) \
    asm volatile("ldmatrix.sync.aligned.m8n8.x4.shared.b16 {%0,%1,%2,%3}, [%4];" \
                 : "=r"(r0), "=r"(r1), "=r"(r2), "=r"(r3) : "r"(addr))

#define MMA16816(d, a0, a1, a2, a3, b0, b1) \
    asm volatile("mma.sync.aligned.m16n8k16.row.col.f32.f16.f16.f32 " \
                 "{%0,%1,%2,%3}, {%4,%5,%6,%7}, {%8,%9}, {%0,%1,%2,%3};" \
                 : "+f"((d)[0]), "+f"((d)[1]), "+f"((d)[2]), "+f"((d)[3]) \
                 : "r"(a0), "r"(a1), "r"(a2), "r"(a3), "r"(b0), "r"(b1))

#define CP_ASYNC16(dst, src) \
    asm volatile("cp.async.cg.shared.global [%0], [%1], 16;" :: "r"(dst), "l"(src))
#define CP_COMMIT()  asm volatile("cp.async.commit_group;" ::: "memory")
#define CP_WAIT0()   asm volatile("cp.async.wait_group 0;" ::: "memory")

#define FMA2(acc, x, y) asm("fma.rn.f32x2 %0, %1, %2, %0;" : "+l"(acc) : "l"(x), "l"(y))
#define PACK2(d, f)     asm("mov.b64 %0, {%1, %1};" : "=l"(d) : "f"(f))
#define UNPACK2(lo, hi, v) asm("mov.b64 {%0, %1}, %2;" : "=f"(lo), "=f"(hi) : "l"(v))

// ---------------------------------------------------------------------------
// Kernel A: wh in registers (FFMA2 inner loop) -> whT fp16 + src/dst.
// ---------------------------------------------------------------------------
__global__ __launch_bounds__(256) void k_proj(const float* __restrict__ inp,
                                              const float* __restrict__ W,
                                              const float* __restrict__ bW,
                                              const float* __restrict__ av,
                                              const float* __restrict__ b_a) {
    __shared__ __align__(16) float A_s[32 * 132];
    __shared__ __align__(16) float W_s[32 * 132];
    int t = threadIdx.x;
    int row0 = blockIdx.x * 128;
    int tr = t >> 4, tc = t & 15;

    ull acc2[4][8];   // row-pairs (2*i2, 2*i2+1) x 8 j-cols
#pragma unroll
    for (int i2 = 0; i2 < 4; i2++)
#pragma unroll
        for (int j = 0; j < 8; j++) acc2[i2][j] = 0ull;

    for (int k0 = 0; k0 < FIN; k0 += 32) {
#pragma unroll
        for (int v = 0; v < 4; v++) {
            int f4 = t + 256 * v;
            int r = f4 >> 3;
            int c = (f4 & 7) * 4;
            float4 a4 = *(const float4*)(inp + (size_t)(row0 + r) * FIN + k0 + c);
            A_s[(c + 0) * 132 + r] = a4.x;
            A_s[(c + 1) * 132 + r] = a4.y;
            A_s[(c + 2) * 132 + r] = a4.z;
            A_s[(c + 3) * 132 + r] = a4.w;
            float4 b4 = *(const float4*)(W + (size_t)r * FIN + k0 + c);
            W_s[(c + 0) * 132 + r] = b4.x;
            W_s[(c + 1) * 132 + r] = b4.y;
            W_s[(c + 2) * 132 + r] = b4.z;
            W_s[(c + 3) * 132 + r] = b4.w;
        }
        __syncthreads();
#pragma unroll
        for (int kk = 0; kk < 32; kk++) {
            // a row-pairs (16B aligned: (kk*132 + tr*8)*4 = 528kk + 32tr)
            ulonglong2 aA = *(const ulonglong2*)&A_s[kk * 132 + tr * 8];
            ulonglong2 aB = *(const ulonglong2*)&A_s[kk * 132 + tr * 8 + 4];
            float b[8];
            *(float4*)&b[0] = *(const float4*)&W_s[kk * 132 + tc * 8];
            *(float4*)&b[4] = *(const float4*)&W_s[kk * 132 + tc * 8 + 4];
            ull bd[8];
#pragma unroll
            for (int j = 0; j < 8; j++) PACK2(bd[j], b[j]);
#pragma unroll
            for (int j = 0; j < 8; j++) {
                FMA2(acc2[0][j], aA.x, bd[j]);
                FMA2(acc2[1][j], aA.y, bd[j]);
                FMA2(acc2[2][j], aB.x, bd[j]);
                FMA2(acc2[3][j], aB.y, bd[j]);
            }
        }
        __syncthreads();
    }

    // unpack to scalar accumulator grid (rows i = 2*i2 + lane)
    float acc[8][8];
#pragma unroll
    for (int i2 = 0; i2 < 4; i2++)
#pragma unroll
        for (int j = 0; j < 8; j++)
            UNPACK2(acc[2 * i2][j], acc[2 * i2 + 1][j], acc2[i2][j]);

    // ---- epilogue (unchanged) ----
    int h0 = tc * 8;
    int bb = row0 / N_;
    int n0 = (row0 % N_) + tr * 8;

    float bwv[8];
    *(float4*)&bwv[0] = *(const float4*)(bW + h0);
    *(float4*)&bwv[4] = *(const float4*)(bW + h0 + 4);
#pragma unroll
    for (int i = 0; i < 8; i++)
#pragma unroll
        for (int j = 0; j < 8; j++) acc[i][j] += bwv[j];

    // whT transposed fp16 stores
#pragma unroll
    for (int j = 0; j < 8; j++) {
        __align__(16) half hi8[8];
#pragma unroll
        for (int i = 0; i < 8; i++) hi8[i] = __float2half_rn(acc[i][j]);
        size_t idx = ((size_t)(bb * H_ + h0 + j)) * N_ + n0;
        *(uint4*)(g_whT + idx) = *(uint4*)hi8;
    }

    // src/dst reductions
    float a1v[8], a2v[8];
    *(float4*)&a1v[0] = *(const float4*)(av + h0);
    *(float4*)&a1v[4] = *(const float4*)(av + h0 + 4);
    *(float4*)&a2v[0] = *(const float4*)(av + H_ + h0);
    *(float4*)&a2v[4] = *(const float4*)(av + H_ + h0 + 4);

    float s1[8], s2[8];
#pragma unroll
    for (int i = 0; i < 8; i++) {
        float x1 = 0.f, x2 = 0.f;
#pragma unroll
        for (int j = 0; j < 8; j++) {
            x1 = fmaf(acc[i][j], a1v[j], x1);
            x2 = fmaf(acc[i][j], a2v[j], x2);
        }
        s1[i] = x1; s2[i] = x2;
    }
#pragma unroll
    for (int o = 1; o < 16; o <<= 1) {
#pragma unroll
        for (int i = 0; i < 8; i++) {
            s1[i] += __shfl_xor_sync(~0u, s1[i], o);
            s2[i] += __shfl_xor_sync(~0u, s2[i], o);
        }
    }
    if (tc == 0) {
        float ba = b_a[0];
        int r = row0 + tr * 8;
#pragma unroll
        for (int i = 0; i < 8; i++) {
            g_src[r + i] = s1[i] + ba;
            g_dst[r + i] = s2[i];
        }
    }
}

// ---------------------------------------------------------------------------
// Kernel P: pack adj (int32 0/1) into bitmasks.
// ---------------------------------------------------------------------------
__global__ __launch_bounds__(256) void k_pack(const int* __restrict__ adj) {
    int row = blockIdx.x * 8 + (threadIdx.x >> 5);
    int lane = threadIdx.x & 31;
    const int* r = adj + (size_t)row * N_;
    uint32_t* o = g_adjb + (size_t)row * 64;
#pragma unroll
    for (int g = 0; g < 8; g++) {
        int v[8];
#pragma unroll
        for (int k = 0; k < 8; k++) v[k] = r[g * 256 + k * 32 + lane];
        uint32_t msk[8];
#pragma unroll
        for (int k = 0; k < 8; k++) msk[k] = __ballot_sync(~0u, v[k] > 0);
        if (lane == 0) {
            *(uint4*)(o + g * 8)     = make_uint4(msk[0], msk[1], msk[2], msk[3]);
            *(uint4*)(o + g * 8 + 4) = make_uint4(msk[4], msk[5], msk[6], msk[7]);
        }
    }
}

// ---------------------------------------------------------------------------
// Kernel B2: per-batch dst max + exp tables ed1 = exp(dst), ed0 = exp(.01 dst)
// ---------------------------------------------------------------------------
__global__ __launch_bounds__(256) void k_prep() {
    __shared__ float red[8];
    int b = blockIdx.x, t = threadIdx.x;
    float mx = -1e30f;
#pragma unroll
    for (int v = 0; v < 8; v++) {
        int idx = b * N_ + t + 256 * v;
        float d = g_dst[idx];
        mx = fmaxf(mx, d);
        g_ed[idx] = make_float2(__expf(d), __expf(0.01f * d));
    }
#pragma unroll
    for (int o = 16; o; o >>= 1) mx = fmaxf(mx, __shfl_xor_sync(~0u, mx, o));
    if ((t & 31) == 0) red[t >> 5] = mx;
    __syncthreads();
    if (t == 0) {
        float m2 = red[0];
#pragma unroll
        for (int i = 1; i < 8; i++) m2 = fmaxf(m2, red[i]);
        g_dstmax[b] = m2;
    }
}

// ---------------------------------------------------------------------------
// Kernel C: fused attention. Score phase has NO exp (table factorization):
//   p = mask ? (ed1[j] > X1 ? E1*ed1[j] : E0*ed0[j]) : 0
//
// smem: Ph[2]: 0,18432  W[2]: 36864,55296  ed: 73728 (16KB)  l_s: 90112
// total 90624.  Row stride 144B (ldmatrix conflict-free).
// ---------------------------------------------------------------------------
#define PB   18432u
#define OWH  36864u
#define OED  73728u
#define OLS  90112u
#define DYNB 90624

__global__ __launch_bounds__(256, 2) void k_attn_mma(float* __restrict__ out) {
    extern __shared__ __align__(16) char dyn[];
    uint32_t sb = smem_u32(dyn);

    int t = threadIdx.x;
    int w = t >> 5, lane = t & 31;
    int ti = t >> 1, q = t & 1;
    int b = blockIdx.y;
    int ibase = blockIdx.x * 128;

    float my_src = g_src[b * N_ + ibase + ti];
    float mb = my_src + g_dstmax[b];
    float m = mb > 0.f ? mb : 0.01f * mb;
    float E1 = __expf(my_src - m);
    float E0 = __expf(0.01f * my_src - m);
    float X1 = __expf(-my_src);
    float l = 0.f;

    const uint32_t* adjb_row = g_adjb + (size_t)(b * N_ + ibase + ti) * 64;
    const half*     whT_b    = g_whT + (size_t)b * H_ * N_;

    float C[16][4];
#pragma unroll
    for (int nt = 0; nt < 16; nt++)
#pragma unroll
        for (int c = 0; c < 4; c++) C[nt][c] = 0.f;

    // ldmatrix base addresses (buffer 0), row stride 144B
    uint32_t a_base = sb + (16 * w + (lane & 15)) * 144 + (lane >> 4) * 16;  // Ph
    int bn = ((lane >> 4) & 1) * 8 + (lane & 7);
    int bk = ((lane >> 3) & 1) * 8;
    uint32_t b_base = sb + OWH + bn * 144 + bk * 2;                           // W

    // W staging: 2 threads per row, 4 x 16B chunks each (128B/row)
    int hr = t >> 1, hf = t & 1;
    uint32_t wdst = sb + OWH + hr * 144 + hf * 64;
    const half* wsrc = whT_b + (size_t)hr * N_ + hf * 32;

    // ---- prologue: stage W(0), ed table -> smem, mask(0) ----
#pragma unroll
    for (int k = 0; k < 4; k++) CP_ASYNC16(wdst + k * 16, wsrc + k * 8);
    CP_COMMIT();
    {
        float4* ds = (float4*)(dyn + OED);
        const float4* g4 = (const float4*)(g_ed + b * N_);
#pragma unroll
        for (int k = 0; k < 4; k++) ds[t + 256 * k] = g4[t + 256 * k];
    }
    uint32_t mnext = adjb_row[q];
    __syncthreads();   // ed_s visible

    for (int tile = 0; tile < NTILE; tile++) {
        int s = tile & 1;
        int j0 = tile * TJ;

        // ---- score phase: 32 j's = [j0 + q*32, +32) for row ti ----
        {
            uint32_t mask = mnext;
            if (tile < NTILE - 1) mnext = adjb_row[(tile + 1) * 2 + q];

            const float4* e4 = (const float4*)(dyn + OED) + ((j0 + q * 32) >> 1);
            __align__(16) half hs[32];
#pragma unroll
            for (int v = 0; v < 16; v++) {       // 2 j's per float4 (e1,e0,e1,e0)
                float4 ee = e4[v];
                float pa = (ee.x > X1) ? E1 * ee.x : E0 * ee.y;
                float pb = (ee.z > X1) ? E1 * ee.z : E0 * ee.w;
                pa = (mask >> (2 * v + 0)) & 1 ? pa : 0.f;
                pb = (mask >> (2 * v + 1)) & 1 ? pb : 0.f;
                l += pa + pb;
                *(half2*)&hs[2 * v] = __floats2half2_rn(pa, pb);
            }
            uint32_t poff = s * PB + ti * 144 + q * 64;
#pragma unroll
            for (int k = 0; k < 4; k++)
                *(uint4*)(dyn + poff + k * 16) = ((uint4*)hs)[k];
        }

        CP_WAIT0();        // W(tile) landed
        __syncthreads();   // P(s) visible; MMA(tile-1) done with buffer s^1

        // ---- stage W(tile+1) into buffer s^1 (overlaps MMA) ----
        if (tile < NTILE - 1) {
            int jn = (tile + 1) * TJ;
            uint32_t off = (s ^ 1) * PB;
#pragma unroll
            for (int k = 0; k < 4; k++) CP_ASYNC16(wdst + off + k * 16, wsrc + jn + k * 8);
            CP_COMMIT();
        }

        // ---- MMA phase on buffer s: 4 k16 chunks ----
        uint32_t aoff = s * PB;
#pragma unroll
        for (int kc = 0; kc < 4; kc++) {
            uint32_t Ah0, Ah1, Ah2, Ah3;
            LDSM4(Ah0, Ah1, Ah2, Ah3, a_base + aoff + kc * 32);
#pragma unroll
            for (int np = 0; np < 8; np++) {
                uint32_t Bh0, Bh1, Bh2, Bh3;
                LDSM4(Bh0, Bh1, Bh2, Bh3, b_base + aoff + np * (16 * 144) + kc * 32);
                MMA16816(C[np * 2 + 0], Ah0, Ah1, Ah2, Ah3, Bh0, Bh1);
                MMA16816(C[np * 2 + 1], Ah0, Ah1, Ah2, Ah3, Bh2, Bh3);
            }
        }
    }

    l += __shfl_xor_sync(~0u, l, 1);
    float* l_s = (float*)(dyn + OLS);
    if (q == 0) l_s[ti] = l;
    __syncthreads();

    // ---- epilogue: normalize, ELU, store from fragments ----
    {
        int r0 = 16 * w + (lane >> 2);
        int r1 = r0 + 8;
        float inv0 = 1.0f / l_s[r0];
        float inv1 = 1.0f / l_s[r1];
        float* orow0 = out + ((size_t)(b * N_ + ibase + r0)) * H_;
        float* orow1 = out + ((size_t)(b * N_ + ibase + r1)) * H_;
        int hoff = (lane & 3) * 2;
#pragma unroll
        for (int nt = 0; nt < 16; nt++) {
            int h = nt * 8 + hoff;
            float x;
            float2 o;
            x = C[nt][0] * inv0; o.x = x > 0.f ? x : expm1f(x);
            x = C[nt][1] * inv0; o.y = x > 0.f ? x : expm1f(x);
            *(float2*)(orow0 + h) = o;
            x = C[nt][2] * inv1; o.x = x > 0.f ? x : expm1f(x);
            x = C[nt][3] * inv1; o.y = x > 0.f ? x : expm1f(x);
            *(float2*)(orow1 + h) = o;
        }
    }
}

// ---------------------------------------------------------------------------
extern "C" void kernel_launch(void* const* d_in, const int* in_sizes, int n_in,
                              void* d_out, int out_size) {
    const float* inputs = (const float*)d_in[0];
    const int*   adj    = (const int*)d_in[1];
    const float* W      = (const float*)d_in[2];
    const float* bW     = (const float*)d_in[3];
    const float* a      = (const float*)d_in[4];
    const float* b_a    = (const float*)d_in[5];
    float* out = (float*)d_out;

    cudaFuncSetAttribute(k_attn_mma, cudaFuncAttributeMaxDynamicSharedMemorySize, DYNB);

    k_proj<<<(B_ * N_) / 128, 256>>>(inputs, W, bW, a, b_a);
    k_pack<<<(B_ * N_) / 8, 256>>>(adj);
    k_prep<<<B_, 256>>>();
    k_attn_mma<<<dim3(N_ / 128, B_), 256, DYNB>>>(out);
}

// round 16
// speedup vs baseline: 1.1663x; 1.0612x over previous
#include <cuda_runtime.h>
#include <cuda_fp16.h>
#include <cstdint>
#include <math.h>

#define B_   16
#define N_   2048
#define FIN  256
#define H_   128
#define TJ   64
#define NTILE (N_ / TJ)      // 32

// Scratch (allocation-free: __device__ globals)
__device__ half     g_whT[B_ * H_ * N_];      // [b][h][n] fp16
__device__ float    g_src[B_ * N_];           // src + b_a folded in
__device__ float    g_dst[B_ * N_];
__device__ float    g_dstmax[B_];
__device__ float2   g_ed[B_ * N_];            // (exp(dst), exp(0.01*dst))
__device__ uint32_t g_adjb[B_ * N_ * 64];     // bit-packed adj, 64 u32 per row

__device__ __forceinline__ uint32_t smem_u32(const void* p) {
    uint32_t a;
    asm("{ .reg .u64 t; cvta.to.shared.u64 t, %1; cvt.u32.u64 %0, t; }" : "=r"(a) : "l"(p));
    return a;
}

#define LDSM4(r0, r1, r2, r3, addr) \
    asm volatile("ldmatrix.sync.aligned.m8n8.x4.shared.b16 {%0,%1,%2,%3}, [%4];" \
                 : "=r"(r0), "=r"(r1), "=r"(r2), "=r"(r3) : "r"(addr))

#define MMA16816(d, a0, a1, a2, a3, b0, b1) \
    asm volatile("mma.sync.aligned.m16n8k16.row.col.f32.f16.f16.f32 " \
                 "{%0,%1,%2,%3}, {%4,%5,%6,%7}, {%8,%9}, {%0,%1,%2,%3};" \
                 : "+f"((d)[0]), "+f"((d)[1]), "+f"((d)[2]), "+f"((d)[3]) \
                 : "r"(a0), "r"(a1), "r"(a2), "r"(a3), "r"(b0), "r"(b1))

#define CP_ASYNC16(dst, src) \
    asm volatile("cp.async.cg.shared.global [%0], [%1], 16;" :: "r"(dst), "l"(src))
#define CP_COMMIT()  asm volatile("cp.async.commit_group;" ::: "memory")
#define CP_WAIT0()   asm volatile("cp.async.wait_group 0;" ::: "memory")

// ---------------------------------------------------------------------------
// Kernel A: wh in registers -> whT fp16 plane + src/dst reductions (scalar
// FFMA inner loop — round-13 version; FFMA2 variant measured neutral-worse).
// ---------------------------------------------------------------------------
__global__ __launch_bounds__(256) void k_proj(const float* __restrict__ inp,
                                              const float* __restrict__ W,
                                              const float* __restrict__ bW,
                                              const float* __restrict__ av,
                                              const float* __restrict__ b_a) {
    __shared__ __align__(16) float A_s[32 * 132];
    __shared__ __align__(16) float W_s[32 * 132];
    int t = threadIdx.x;
    int row0 = blockIdx.x * 128;
    int tr = t >> 4, tc = t & 15;

    float acc[8][8];
#pragma unroll
    for (int i = 0; i < 8; i++)
#pragma unroll
        for (int j = 0; j < 8; j++) acc[i][j] = 0.f;

    for (int k0 = 0; k0 < FIN; k0 += 32) {
#pragma unroll
        for (int v = 0; v < 4; v++) {
            int f4 = t + 256 * v;
            int r = f4 >> 3;
            int c = (f4 & 7) * 4;
            float4 a4 = *(const float4*)(inp + (size_t)(row0 + r) * FIN + k0 + c);
            A_s[(c + 0) * 132 + r] = a4.x;
            A_s[(c + 1) * 132 + r] = a4.y;
            A_s[(c + 2) * 132 + r] = a4.z;
            A_s[(c + 3) * 132 + r] = a4.w;
            float4 b4 = *(const float4*)(W + (size_t)r * FIN + k0 + c);
            W_s[(c + 0) * 132 + r] = b4.x;
            W_s[(c + 1) * 132 + r] = b4.y;
            W_s[(c + 2) * 132 + r] = b4.z;
            W_s[(c + 3) * 132 + r] = b4.w;
        }
        __syncthreads();
#pragma unroll
        for (int kk = 0; kk < 32; kk++) {
            float a[8], b[8];
            *(float4*)&a[0] = *(const float4*)&A_s[kk * 132 + tr * 8];
            *(float4*)&a[4] = *(const float4*)&A_s[kk * 132 + tr * 8 + 4];
            *(float4*)&b[0] = *(const float4*)&W_s[kk * 132 + tc * 8];
            *(float4*)&b[4] = *(const float4*)&W_s[kk * 132 + tc * 8 + 4];
#pragma unroll
            for (int i = 0; i < 8; i++)
#pragma unroll
                for (int j = 0; j < 8; j++)
                    acc[i][j] = fmaf(a[i], b[j], acc[i][j]);
        }
        __syncthreads();
    }

    // ---- epilogue ----
    int h0 = tc * 8;
    int bb = row0 / N_;
    int n0 = (row0 % N_) + tr * 8;

    float bwv[8];
    *(float4*)&bwv[0] = *(const float4*)(bW + h0);
    *(float4*)&bwv[4] = *(const float4*)(bW + h0 + 4);
#pragma unroll
    for (int i = 0; i < 8; i++)
#pragma unroll
        for (int j = 0; j < 8; j++) acc[i][j] += bwv[j];

    // whT transposed fp16 stores
#pragma unroll
    for (int j = 0; j < 8; j++) {
        __align__(16) half hi8[8];
#pragma unroll
        for (int i = 0; i < 8; i++) hi8[i] = __float2half_rn(acc[i][j]);
        size_t idx = ((size_t)(bb * H_ + h0 + j)) * N_ + n0;
        *(uint4*)(g_whT + idx) = *(uint4*)hi8;
    }

    // src/dst reductions
    float a1v[8], a2v[8];
    *(float4*)&a1v[0] = *(const float4*)(av + h0);
    *(float4*)&a1v[4] = *(const float4*)(av + h0 + 4);
    *(float4*)&a2v[0] = *(const float4*)(av + H_ + h0);
    *(float4*)&a2v[4] = *(const float4*)(av + H_ + h0 + 4);

    float s1[8], s2[8];
#pragma unroll
    for (int i = 0; i < 8; i++) {
        float x1 = 0.f, x2 = 0.f;
#pragma unroll
        for (int j = 0; j < 8; j++) {
            x1 = fmaf(acc[i][j], a1v[j], x1);
            x2 = fmaf(acc[i][j], a2v[j], x2);
        }
        s1[i] = x1; s2[i] = x2;
    }
#pragma unroll
    for (int o = 1; o < 16; o <<= 1) {
#pragma unroll
        for (int i = 0; i < 8; i++) {
            s1[i] += __shfl_xor_sync(~0u, s1[i], o);
            s2[i] += __shfl_xor_sync(~0u, s2[i], o);
        }
    }
    if (tc == 0) {
        float ba = b_a[0];
        int r = row0 + tr * 8;
#pragma unroll
        for (int i = 0; i < 8; i++) {
            g_src[r + i] = s1[i] + ba;
            g_dst[r + i] = s2[i];
        }
    }
}

// ---------------------------------------------------------------------------
// Kernel P: pack adj (int32 0/1) into bitmasks.
// ---------------------------------------------------------------------------
__global__ __launch_bounds__(256) void k_pack(const int* __restrict__ adj) {
    int row = blockIdx.x * 8 + (threadIdx.x >> 5);
    int lane = threadIdx.x & 31;
    const int* r = adj + (size_t)row * N_;
    uint32_t* o = g_adjb + (size_t)row * 64;
#pragma unroll
    for (int g = 0; g < 8; g++) {
        int v[8];
#pragma unroll
        for (int k = 0; k < 8; k++) v[k] = r[g * 256 + k * 32 + lane];
        uint32_t msk[8];
#pragma unroll
        for (int k = 0; k < 8; k++) msk[k] = __ballot_sync(~0u, v[k] > 0);
        if (lane == 0) {
            *(uint4*)(o + g * 8)     = make_uint4(msk[0], msk[1], msk[2], msk[3]);
            *(uint4*)(o + g * 8 + 4) = make_uint4(msk[4], msk[5], msk[6], msk[7]);
        }
    }
}

// ---------------------------------------------------------------------------
// Kernel B2: per-batch dst max + exp tables ed1 = exp(dst), ed0 = exp(.01 dst)
// ---------------------------------------------------------------------------
__global__ __launch_bounds__(256) void k_prep() {
    __shared__ float red[8];
    int b = blockIdx.x, t = threadIdx.x;
    float mx = -1e30f;
#pragma unroll
    for (int v = 0; v < 8; v++) {
        int idx = b * N_ + t + 256 * v;
        float d = g_dst[idx];
        mx = fmaxf(mx, d);
        g_ed[idx] = make_float2(__expf(d), __expf(0.01f * d));
    }
#pragma unroll
    for (int o = 16; o; o >>= 1) mx = fmaxf(mx, __shfl_xor_sync(~0u, mx, o));
    if ((t & 31) == 0) red[t >> 5] = mx;
    __syncthreads();
    if (t == 0) {
        float m2 = red[0];
#pragma unroll
        for (int i = 1; i < 8; i++) m2 = fmaxf(m2, red[i]);
        g_dstmax[b] = m2;
    }
}

// ---------------------------------------------------------------------------
// Kernel C: fused attention, P computed DIRECTLY in MMA A-fragment layout —
// no P smem round-trip. Each thread owns rows (r0=16w+lane/4, r1=r0+8) and
// j cols 2c,2c+1,2c+8,2c+9 per k16 chunk (c=lane%4). ed reads are warp
// broadcasts (8 distinct float4 per kc); masks are 2 prefetched uint2/tile.
//
// smem: W[2]: 0, 18432   ed: 36864 (16KB)   l_s: 53248   total 53760
// ---------------------------------------------------------------------------
#define PB   18432u
#define OED  36864u
#define OLS  53248u
#define DYNB 53760

__global__ __launch_bounds__(256, 2) void k_attn_mma(float* __restrict__ out) {
    extern __shared__ __align__(16) char dyn[];
    uint32_t sb = smem_u32(dyn);

    int t = threadIdx.x;
    int w = t >> 5, lane = t & 31;
    int b = blockIdx.y;
    int ibase = blockIdx.x * 128;

    int r0 = 16 * w + (lane >> 2);      // fragment row (and r0+8)
    int c4 = lane & 3;

    // per-row constants for both fragment rows
    float srcA = g_src[b * N_ + ibase + r0];
    float srcB = g_src[b * N_ + ibase + r0 + 8];
    float dmx = g_dstmax[b];
    float mbA = srcA + dmx;  float mA = mbA > 0.f ? mbA : 0.01f * mbA;
    float mbB = srcB + dmx;  float mB = mbB > 0.f ? mbB : 0.01f * mbB;
    float E1a = __expf(srcA - mA), E0a = __expf(0.01f * srcA - mA), X1a = __expf(-srcA);
    float E1b = __expf(srcB - mB), E0b = __expf(0.01f * srcB - mB), X1b = __expf(-srcB);
    float lA = 0.f, lB = 0.f;

    const uint32_t* mrowA = g_adjb + (size_t)(b * N_ + ibase + r0) * 64;
    const uint32_t* mrowB = g_adjb + (size_t)(b * N_ + ibase + r0 + 8) * 64;
    const half*     whT_b = g_whT + (size_t)b * H_ * N_;

    float C[16][4];
#pragma unroll
    for (int nt = 0; nt < 16; nt++)
#pragma unroll
        for (int c = 0; c < 4; c++) C[nt][c] = 0.f;

    // B-side ldmatrix base (row stride 144B, conflict-free)
    int bn = ((lane >> 4) & 1) * 8 + (lane & 7);
    int bk = ((lane >> 3) & 1) * 8;
    uint32_t b_base = sb + bn * 144 + bk * 2;

    // W staging: 2 threads per row, 4 x 16B chunks each (128B/row)
    int hr = t >> 1, hf = t & 1;
    uint32_t wdst = sb + hr * 144 + hf * 64;
    const half* wsrc = whT_b + (size_t)hr * N_ + hf * 32;

    // ---- prologue: stage W(0), ed table -> smem, masks(0) ----
#pragma unroll
    for (int k = 0; k < 4; k++) CP_ASYNC16(wdst + k * 16, wsrc + k * 8);
    CP_COMMIT();
    {
        float4* ds = (float4*)(dyn + OED);
        const float4* g4 = (const float4*)(g_ed + b * N_);
#pragma unroll
        for (int k = 0; k < 4; k++) ds[t + 256 * k] = g4[t + 256 * k];
    }
    uint2 mAn = *(const uint2*)(mrowA);
    uint2 mBn = *(const uint2*)(mrowB);
    __syncthreads();   // ed_s visible

    for (int tile = 0; tile < NTILE; tile++) {
        int s = tile & 1;
        int j0 = tile * TJ;

        // ---- score phase: build A fragments in registers ----
        uint32_t afrag[4][4];
        {
            uint2 mA2 = mAn, mB2 = mBn;
            if (tile < NTILE - 1) {
                mAn = *(const uint2*)(mrowA + (tile + 1) * 2);
                mBn = *(const uint2*)(mrowB + (tile + 1) * 2);
            }
            uint32_t slA[4] = {mA2.x & 0xffffu, mA2.x >> 16, mA2.y & 0xffffu, mA2.y >> 16};
            uint32_t slB[4] = {mB2.x & 0xffffu, mB2.x >> 16, mB2.y & 0xffffu, mB2.y >> 16};
            const float4* e4 = (const float4*)(dyn + OED) + (j0 >> 1);
#pragma unroll
            for (int kc = 0; kc < 4; kc++) {
                float4 eA = e4[8 * kc + c4];        // j = 16kc + 2c, 2c+1
                float4 eB = e4[8 * kc + c4 + 4];    // j = 16kc + 2c+8, 2c+9
                int b0 = 2 * c4;
                float p;
                float pA0, pA1, pA2, pA3;   // row r0: cols 2c,2c+1,2c+8,2c+9
                float pB0, pB1, pB2, pB3;   // row r0+8
                p = (eA.x > X1a) ? E1a * eA.x : E0a * eA.y; pA0 = (slA[kc] >> (b0 + 0)) & 1 ? p : 0.f;
                p = (eA.z > X1a) ? E1a * eA.z : E0a * eA.w; pA1 = (slA[kc] >> (b0 + 1)) & 1 ? p : 0.f;
                p = (eB.x > X1a) ? E1a * eB.x : E0a * eB.y; pA2 = (slA[kc] >> (b0 + 8)) & 1 ? p : 0.f;
                p = (eB.z > X1a) ? E1a * eB.z : E0a * eB.w; pA3 = (slA[kc] >> (b0 + 9)) & 1 ? p : 0.f;
                p = (eA.x > X1b) ? E1b * eA.x : E0b * eA.y; pB0 = (slB[kc] >> (b0 + 0)) & 1 ? p : 0.f;
                p = (eA.z > X1b) ? E1b * eA.z : E0b * eA.w; pB1 = (slB[kc] >> (b0 + 1)) & 1 ? p : 0.f;
                p = (eB.x > X1b) ? E1b * eB.x : E0b * eB.y; pB2 = (slB[kc] >> (b0 + 8)) & 1 ? p : 0.f;
                p = (eB.z > X1b) ? E1b * eB.z : E0b * eB.w; pB3 = (slB[kc] >> (b0 + 9)) & 1 ? p : 0.f;
                lA += pA0 + pA1 + pA2 + pA3;
                lB += pB0 + pB1 + pB2 + pB3;
                half2 h;
                h = __floats2half2_rn(pA0, pA1); afrag[kc][0] = *(uint32_t*)&h;
                h = __floats2half2_rn(pB0, pB1); afrag[kc][1] = *(uint32_t*)&h;
                h = __floats2half2_rn(pA2, pA3); afrag[kc][2] = *(uint32_t*)&h;
                h = __floats2half2_rn(pB2, pB3); afrag[kc][3] = *(uint32_t*)&h;
            }
        }

        CP_WAIT0();        // W(tile) landed
        __syncthreads();   // MMA(tile-1) done with buffer s^1

        // ---- stage W(tile+1) into buffer s^1 (overlaps MMA) ----
        if (tile < NTILE - 1) {
            int jn = (tile + 1) * TJ;
            uint32_t off = (s ^ 1) * PB;
#pragma unroll
            for (int k = 0; k < 4; k++) CP_ASYNC16(wdst + off + k * 16, wsrc + jn + k * 8);
            CP_COMMIT();
        }

        // ---- MMA phase on buffer s ----
        uint32_t aoff = s * PB;
#pragma unroll
        for (int kc = 0; kc < 4; kc++) {
#pragma unroll
            for (int np = 0; np < 8; np++) {
                uint32_t Bh0, Bh1, Bh2, Bh3;
                LDSM4(Bh0, Bh1, Bh2, Bh3, b_base + aoff + np * (16 * 144) + kc * 32);
                MMA16816(C[np * 2 + 0], afrag[kc][0], afrag[kc][1], afrag[kc][2], afrag[kc][3], Bh0, Bh1);
                MMA16816(C[np * 2 + 1], afrag[kc][0], afrag[kc][1], afrag[kc][2], afrag[kc][3], Bh2, Bh3);
            }
        }
    }

    // l reduction across the lane quad (4 lanes share each row)
    lA += __shfl_xor_sync(~0u, lA, 1); lA += __shfl_xor_sync(~0u, lA, 2);
    lB += __shfl_xor_sync(~0u, lB, 1); lB += __shfl_xor_sync(~0u, lB, 2);
    float* l_s = (float*)(dyn + OLS);
    if (c4 == 0) {
        l_s[r0] = lA;
        l_s[r0 + 8] = lB;
    }
    __syncthreads();

    // ---- epilogue: normalize, ELU, store from fragments ----
    {
        float inv0 = 1.0f / l_s[r0];
        float inv1 = 1.0f / l_s[r0 + 8];
        float* orow0 = out + ((size_t)(b * N_ + ibase + r0)) * H_;
        float* orow1 = out + ((size_t)(b * N_ + ibase + r0 + 8)) * H_;
        int hoff = c4 * 2;
#pragma unroll
        for (int nt = 0; nt < 16; nt++) {
            int h = nt * 8 + hoff;
            float x;
            float2 o;
            x = C[nt][0] * inv0; o.x = x > 0.f ? x : expm1f(x);
            x = C[nt][1] * inv0; o.y = x > 0.f ? x : expm1f(x);
            *(float2*)(orow0 + h) = o;
            x = C[nt][2] * inv1; o.x = x > 0.f ? x : expm1f(x);
            x = C[nt][3] * inv1; o.y = x > 0.f ? x : expm1f(x);
            *(float2*)(orow1 + h) = o;
        }
    }
}

// ---------------------------------------------------------------------------
extern "C" void kernel_launch(void* const* d_in, const int* in_sizes, int n_in,
                              void* d_out, int out_size) {
    const float* inputs = (const float*)d_in[0];
    const int*   adj    = (const int*)d_in[1];
    const float* W      = (const float*)d_in[2];
    const float* bW     = (const float*)d_in[3];
    const float* a      = (const float*)d_in[4];
    const float* b_a    = (const float*)d_in[5];
    float* out = (float*)d_out;

    cudaFuncSetAttribute(k_attn_mma, cudaFuncAttributeMaxDynamicSharedMemorySize, DYNB);

    k_proj<<<(B_ * N_) / 128, 256>>>(inputs, W, bW, a, b_a);
    k_pack<<<(B_ * N_) / 8, 256>>>(adj);
    k_prep<<<B_, 256>>>();
    k_attn_mma<<<dim3(N_ / 128, B_), 256, DYNB>>>(out);
}